// round 14
// baseline (speedup 1.0000x reference)
#include <cuda_runtime.h>
#include <math.h>

#define N_EDGES 3200000
#define N_SG    800000
#define T       256
#define EPT     2                        // edges per thread
#define EPB     (T * EPT)                // 512
#define ATT_B   (N_EDGES / EPB)          // 6250
#define SG_BLK  ((N_SG + EPB - 1) / EPB) // 1563 blocks cover softmax region
#define NQ      (N_SG / 4)               // 200000 quads to normalize
#define NORM_BLKS ((NQ + T - 1) / T)     // 782 norm-helper blocks
#define NORM_BASE (ATT_B - NORM_BLKS)    // 5468: helpers are the LAST blocks

__device__ float g_partials[SG_BLK];
__device__ float g_inv;
__device__ unsigned g_done = 0;       // region-partial ticket
__device__ unsigned g_ready = 0;      // g_inv published flag
__device__ unsigned g_norm_done = 0;  // norm-block ticket (for reset)

// rule r = a*3+b  (degrees formulation — best accuracy)
__constant__ float c_mat0[9] = {-0.2f, -0.1f, -0.05f, -0.05f, -0.05f, -0.01f, -0.055f, -0.01f, 0.0f};
__constant__ float c_mat1[9] = {0.0f, -0.002f, -0.001f, -0.001f, -0.001f, -0.0002f, 0.0008f, -0.0002f, 0.0f};
__constant__ float c_bias[9] = {1.0f, 0.7f, 0.275f, 0.4f, 0.25f, 0.07f, 0.2225f, 0.07f, 0.0f};

__device__ __forceinline__ float edge_attention(float4 fs, float4 fd) {
    float d0 = fd.x - fs.x;
    float d1 = fd.y - fs.y;
    float v0 = fd.z - fs.z;
    float v1 = fd.w - fs.w;

    float r2 = d0 * d0 + d1 * d1;
    float q2 = v0 * v0 + v1 * v1;
    float x1 = (r2 > 0.0f) ? r2 * rsqrtf(r2) : 0.0f;
    // cos = dot * rsqrt(r2*q2); |cos|<=1 by Cauchy-Schwarz, clamp catches
    // rounding; rq==0 (degenerate edges) -> cos=0, matching reference path.
    float dot = d0 * v0 + d1 * v1;
    float rq = r2 * q2;
    float cosv = (rq > 0.0f) ? dot * rsqrtf(rq) : 0.0f;
    cosv = fminf(fmaxf(cosv, -1.0f + 1e-6f), 1.0f - 1e-6f);

    // acos(|x|) = sqrt(1-|x|) * p3(|x|)  (A&S 4.4.45, |err| <= 5e-5 rad)
    float ax = fabsf(cosv);
    float p = -0.0187293f;
    p = fmaf(p, ax, 0.0742610f);
    p = fmaf(p, ax, -0.2121144f);
    p = fmaf(p, ax, 1.5707288f);
    float u = 1.0f - ax;                 // >= 1e-6 after clamp
    float sq = u * rsqrtf(u);            // sqrt(1-|x|)
    float r = sq * p;                    // acos(|x|) in [0, pi/2]
    float ang = (cosv >= 0.0f) ? r : (3.14159265358979f - r);
    float x2 = ang * 57.29577951308232f; // degrees

    // memberships as exp2(quadratic) -- shared square, 1 EX2 each
    float w1 = x1 * x1;
    float w2 = x2 * x2;
    float a0 = -1.28239556f * w1;
    float b0 = -8.0149724e-4f * w2;
    float m1[3], m2[3];
    m1[0] = exp2f(a0);
    m1[1] = exp2f(fmaf(5.12958224f, x1, a0 - 5.12958224f));    // center 2
    m1[2] = exp2f(fmaf(10.2591645f, x1, a0 - 20.5183290f));    // center 4
    m2[0] = exp2f(b0);
    m2[1] = exp2f(fmaf(0.144269504f, x2, b0 - 6.49212767f));   // center 90
    m2[2] = exp2f(fmaf(0.288539008f, x2, b0 - 25.9685107f));   // center 180

    float num = 0.0f, den = 0.0f;
#pragma unroll
    for (int a = 0; a < 3; a++) {
#pragma unroll
        for (int b = 0; b < 3; b++) {
            int rr = a * 3 + b;
            float tr = fminf(m1[a], m2[b]);
            float cons = fmaf(x1, c_mat0[rr], fmaf(x2, c_mat1[rr], c_bias[rr]));
            num = fmaf(tr, cons, num);
            den += tr;
        }
    }
    return __fdividef(num, den);
}

__device__ __forceinline__ float block_reduce_sum_256(float v, float* smem) {
#pragma unroll
    for (int off = 16; off > 0; off >>= 1)
        v += __shfl_xor_sync(0xFFFFFFFFu, v, off);
    int wid = threadIdx.x >> 5;
    int lid = threadIdx.x & 31;
    if (lid == 0) smem[wid] = v;
    __syncthreads();
    if (wid == 0) {
        v = (lid < 8) ? smem[lid] : 0.0f;
#pragma unroll
        for (int off = 4; off > 0; off >>= 1)
            v += __shfl_xor_sync(0xFFFFFFFFu, v, off);
    }
    return v;  // valid in thread 0
}

// Single fused kernel (R11 structure):
//  blocks 0..1562          : edges + exp + partials; last ticket publishes g_inv
//  blocks 1563..5467       : edges only
//  blocks 5468..6249 (LAST): edges, then (zero-wait by then) normalize a slice
__global__ void __launch_bounds__(T, 7) fused_attn_kernel(
        const float4* __restrict__ feat,
        const int2* __restrict__ src2,
        const int2* __restrict__ dst2,
        float* __restrict__ out) {
    __shared__ float smem[8];
    __shared__ bool s_last;
    int t = blockIdx.x * T + threadIdx.x;   // pair index
    int e0 = t * 2;

    int2 s2 = __ldg(&src2[t]);
    int2 d2 = __ldg(&dst2[t]);

    float4 fs0 = __ldg(&feat[s2.x]);
    float4 fd0 = __ldg(&feat[d2.x]);
    float4 fs1 = __ldg(&feat[s2.y]);
    float4 fd1 = __ldg(&feat[d2.y]);

    float2 att;
    att.x = edge_attention(fs0, fd0);
    att.y = edge_attention(fs1, fd1);

    if (blockIdx.x < SG_BLK) {
        float s = 0.0f;
        // N_SG even, e0 even: both edges in or out of the region together
        if (e0 < N_SG) {
            att.x = __expf(att.x);
            att.y = __expf(att.y);
            s = att.x + att.y;
        }
        reinterpret_cast<float2*>(out)[t] = att;
        s = block_reduce_sum_256(s, smem);
        if (threadIdx.x == 0) {
            g_partials[blockIdx.x] = s;
            __threadfence();
            unsigned ticket = atomicAdd(&g_done, 1u);
            s_last = (ticket == SG_BLK - 1);
        }
        __syncthreads();
        if (s_last) {
            float v = 0.0f;
            for (int i = threadIdx.x; i < SG_BLK; i += T)
                v += g_partials[i];
            v = block_reduce_sum_256(v, smem);
            if (threadIdx.x == 0) {
                g_inv = __frcp_rn(v);
                g_done = 0;              // reset ticket for next replay
                __threadfence();
                atomicExch(&g_ready, 1u);
            }
        }
    } else {
        reinterpret_cast<float2*>(out)[t] = att;

        if (blockIdx.x >= NORM_BASE) {
            int nb = blockIdx.x - NORM_BASE;   // 0..781
            // by the last wave g_ready is long since set; spin is a formality
            if (threadIdx.x == 0) {
                while (*(volatile unsigned*)&g_ready == 0u) { __nanosleep(128); }
            }
            __syncthreads();
            __threadfence();
            float inv = g_inv;

            int q = nb * T + threadIdx.x;
            if (q < NQ) {
                float4* out4 = reinterpret_cast<float4*>(out);
                float4 a = out4[q];
                a.x *= inv; a.y *= inv; a.z *= inv; a.w *= inv;
                out4[q] = a;
            }
            // last norm block resets the flag for the next graph replay
            __syncthreads();
            if (threadIdx.x == 0) {
                unsigned nt2 = atomicAdd(&g_norm_done, 1u);
                if (nt2 == NORM_BLKS - 1) {
                    g_norm_done = 0;
                    atomicExch(&g_ready, 0u);
                }
            }
        }
    }
}

extern "C" void kernel_launch(void* const* d_in, const int* in_sizes, int n_in,
                              void* d_out, int out_size) {
    const float4* feat = (const float4*)d_in[0];
    const int2* src2 = (const int2*)d_in[1];
    const int2* dst2 = (const int2*)d_in[2];
    float* out = (float*)d_out;

    fused_attn_kernel<<<ATT_B, T>>>(feat, src2, dst2, out);
}

// round 15
// speedup vs baseline: 1.0553x; 1.0553x over previous
#include <cuda_runtime.h>
#include <math.h>

#define N_EDGES 3200000
#define N_SG    800000
#define T       256
#define EPT     2                        // edges per thread
#define EPB     (T * EPT)                // 512
#define ATT_B   (N_EDGES / EPB)          // 6250
#define SG_BLK  ((N_SG + EPB - 1) / EPB) // 1563 blocks cover softmax region
#define NQ      (N_SG / 4)               // 200000 quads to normalize
#define NORM_BLKS ((NQ + T - 1) / T)     // 782 norm-helper blocks
#define NORM_BASE (ATT_B - NORM_BLKS)    // 5468: helpers are the LAST blocks

__device__ float g_partials[SG_BLK];
__device__ float g_inv;
__device__ unsigned g_done = 0;       // region-partial ticket
__device__ unsigned g_ready = 0;      // g_inv published flag
__device__ unsigned g_norm_done = 0;  // norm-block ticket (for reset)

// rule r = a*3+b  (degrees formulation — best accuracy)
__constant__ float c_mat0[9] = {-0.2f, -0.1f, -0.05f, -0.05f, -0.05f, -0.01f, -0.055f, -0.01f, 0.0f};
__constant__ float c_mat1[9] = {0.0f, -0.002f, -0.001f, -0.001f, -0.001f, -0.0002f, 0.0008f, -0.0002f, 0.0f};
__constant__ float c_bias[9] = {1.0f, 0.7f, 0.275f, 0.4f, 0.25f, 0.07f, 0.2225f, 0.07f, 0.0f};

__device__ __forceinline__ float edge_attention(float4 fs, float4 fd) {
    float d0 = fd.x - fs.x;
    float d1 = fd.y - fs.y;
    float v0 = fd.z - fs.z;
    float v1 = fd.w - fs.w;

    float r2 = d0 * d0 + d1 * d1;
    float q2 = v0 * v0 + v1 * v1;
    float x1 = (r2 > 0.0f) ? r2 * rsqrtf(r2) : 0.0f;
    // cos = dot * rsqrt(r2*q2); |cos|<=1 by Cauchy-Schwarz, clamp catches
    // rounding; rq==0 (degenerate edges) -> cos=0, matching reference path.
    // (validated R13: rel_err 3.63e-7, better than the divide formulation)
    float dot = d0 * v0 + d1 * v1;
    float rq = r2 * q2;
    float cosv = (rq > 0.0f) ? dot * rsqrtf(rq) : 0.0f;
    cosv = fminf(fmaxf(cosv, -1.0f + 1e-6f), 1.0f - 1e-6f);

    // acos(|x|) = sqrt(1-|x|) * p7(|x|), reflect for x<0 (degree-7: accuracy)
    float ax = fabsf(cosv);
    float p = -0.0012624911f;
    p = fmaf(p, ax, 0.0066700901f);
    p = fmaf(p, ax, -0.0170881256f);
    p = fmaf(p, ax, 0.0308918810f);
    p = fmaf(p, ax, -0.0501743046f);
    p = fmaf(p, ax, 0.0889789874f);
    p = fmaf(p, ax, -0.2145988016f);
    p = fmaf(p, ax, 1.5707963050f);
    float u = 1.0f - ax;                 // >= 1e-6 after clamp
    float sq = u * rsqrtf(u);            // sqrt(1-|x|)
    float r = sq * p;                    // acos(|x|) in [0, pi/2]
    float ang = (cosv >= 0.0f) ? r : (3.14159265358979f - r);
    float x2 = ang * 57.29577951308232f; // degrees

    // memberships as exp2(quadratic) -- shared square, 1 EX2 each
    float w1 = x1 * x1;
    float w2 = x2 * x2;
    float a0 = -1.28239556f * w1;
    float b0 = -8.0149724e-4f * w2;
    float m1[3], m2[3];
    m1[0] = exp2f(a0);
    m1[1] = exp2f(fmaf(5.12958224f, x1, a0 - 5.12958224f));    // center 2
    m1[2] = exp2f(fmaf(10.2591645f, x1, a0 - 20.5183290f));    // center 4
    m2[0] = exp2f(b0);
    m2[1] = exp2f(fmaf(0.144269504f, x2, b0 - 6.49212767f));   // center 90
    m2[2] = exp2f(fmaf(0.288539008f, x2, b0 - 25.9685107f));   // center 180

    float num = 0.0f, den = 0.0f;
#pragma unroll
    for (int a = 0; a < 3; a++) {
#pragma unroll
        for (int b = 0; b < 3; b++) {
            int rr = a * 3 + b;
            float tr = fminf(m1[a], m2[b]);
            float cons = fmaf(x1, c_mat0[rr], fmaf(x2, c_mat1[rr], c_bias[rr]));
            num = fmaf(tr, cons, num);
            den += tr;
        }
    }
    return __fdividef(num, den);
}

__device__ __forceinline__ float block_reduce_sum_256(float v, float* smem) {
#pragma unroll
    for (int off = 16; off > 0; off >>= 1)
        v += __shfl_xor_sync(0xFFFFFFFFu, v, off);
    int wid = threadIdx.x >> 5;
    int lid = threadIdx.x & 31;
    if (lid == 0) smem[wid] = v;
    __syncthreads();
    if (wid == 0) {
        v = (lid < 8) ? smem[lid] : 0.0f;
#pragma unroll
        for (int off = 4; off > 0; off >>= 1)
            v += __shfl_xor_sync(0xFFFFFFFFu, v, off);
    }
    return v;  // valid in thread 0
}

// Single fused kernel (R11 structure — measured best):
//  blocks 0..1562          : edges + exp + partials; last ticket publishes g_inv
//  blocks 1563..5467       : edges only
//  blocks 5468..6249 (LAST): edges, then (zero-wait by then) normalize a slice
__global__ void __launch_bounds__(T, 7) fused_attn_kernel(
        const float4* __restrict__ feat,
        const int2* __restrict__ src2,
        const int2* __restrict__ dst2,
        float* __restrict__ out) {
    __shared__ float smem[8];
    __shared__ bool s_last;
    int t = blockIdx.x * T + threadIdx.x;   // pair index
    int e0 = t * 2;

    int2 s2 = __ldg(&src2[t]);
    int2 d2 = __ldg(&dst2[t]);

    float4 fs0 = __ldg(&feat[s2.x]);
    float4 fd0 = __ldg(&feat[d2.x]);
    float4 fs1 = __ldg(&feat[s2.y]);
    float4 fd1 = __ldg(&feat[d2.y]);

    float2 att;
    att.x = edge_attention(fs0, fd0);
    att.y = edge_attention(fs1, fd1);

    if (blockIdx.x < SG_BLK) {
        float s = 0.0f;
        // N_SG even, e0 even: both edges in or out of the region together
        if (e0 < N_SG) {
            att.x = __expf(att.x);
            att.y = __expf(att.y);
            s = att.x + att.y;
        }
        reinterpret_cast<float2*>(out)[t] = att;
        s = block_reduce_sum_256(s, smem);
        if (threadIdx.x == 0) {
            g_partials[blockIdx.x] = s;
            __threadfence();
            unsigned ticket = atomicAdd(&g_done, 1u);
            s_last = (ticket == SG_BLK - 1);
        }
        __syncthreads();
        if (s_last) {
            float v = 0.0f;
            for (int i = threadIdx.x; i < SG_BLK; i += T)
                v += g_partials[i];
            v = block_reduce_sum_256(v, smem);
            if (threadIdx.x == 0) {
                g_inv = __frcp_rn(v);
                g_done = 0;              // reset ticket for next replay
                __threadfence();
                atomicExch(&g_ready, 1u);
            }
        }
    } else {
        reinterpret_cast<float2*>(out)[t] = att;

        if (blockIdx.x >= NORM_BASE) {
            int nb = blockIdx.x - NORM_BASE;   // 0..781
            // by the last wave g_ready is long since set; spin is a formality
            if (threadIdx.x == 0) {
                while (*(volatile unsigned*)&g_ready == 0u) { __nanosleep(128); }
            }
            __syncthreads();
            __threadfence();
            float inv = g_inv;

            int q = nb * T + threadIdx.x;
            if (q < NQ) {
                float4* out4 = reinterpret_cast<float4*>(out);
                float4 a = out4[q];
                a.x *= inv; a.y *= inv; a.z *= inv; a.w *= inv;
                out4[q] = a;
            }
            // last norm block resets the flag for the next graph replay
            __syncthreads();
            if (threadIdx.x == 0) {
                unsigned nt2 = atomicAdd(&g_norm_done, 1u);
                if (nt2 == NORM_BLKS - 1) {
                    g_norm_done = 0;
                    atomicExch(&g_ready, 0u);
                }
            }
        }
    }
}

extern "C" void kernel_launch(void* const* d_in, const int* in_sizes, int n_in,
                              void* d_out, int out_size) {
    const float4* feat = (const float4*)d_in[0];
    const int2* src2 = (const int2*)d_in[1];
    const int2* dst2 = (const int2*)d_in[2];
    float* out = (float*)d_out;

    fused_attn_kernel<<<ATT_B, T>>>(feat, src2, dst2, out);
}